// round 5
// baseline (speedup 1.0000x reference)
#include <cuda_runtime.h>
#include <cuda_bf16.h>
#include <cuda_fp16.h>
#include <math.h>
#include <stdint.h>

// Problem constants
#define BB 2048          // batch
#define NN 4096          // 2*B rows of z
#define DD 512           // half feature dim
#define NHALF 12         // 6 inputs x 2 halves
#define NLOSS 9          // contrastive losses
#define NORTHO 12        // ortho pairs
#define TINV 5.0f        // 1/temperature
// sqrt(TINV * log2(e)) folded into bf16 operands => acc = sim*TINV*log2e
#define SCALE_K  2.6857913787767947f
#define SCALE_K2 7.2134752044448170f   // TINV*log2(e)
#define LN2      0.6931471805599453f

// Scratch (device globals; no allocation allowed)
__device__ __nv_bfloat16 g_zhi[NHALF * BB * DD];   // bf16 normalized * SCALE_K
__device__ float         g_rowsum[NLOSS * NN];     // per-row sum of exp(sim/T)

__constant__ int c_cpA[NLOSS] = {0, 0, 2, 6, 6,  8, 1, 3, 5};
__constant__ int c_cpB[NLOSS] = {2, 4, 4, 8, 10, 10, 7, 9, 11};
__constant__ int c_opA[NORTHO] = {0, 2, 4, 1, 1, 3, 6, 8, 10, 7, 7, 9};
__constant__ int c_opB[NORTHO] = {1, 3, 5, 3, 5, 5, 7, 9, 11, 9, 11, 11};

// ---------------------------------------------------------------------------
__device__ __forceinline__ uint32_t smem_u32(const void* p) {
    uint32_t a;
    asm("{ .reg .u64 t; cvta.to.shared.u64 t, %1; cvt.u32.u64 %0, t; }" : "=r"(a) : "l"(p));
    return a;
}
__device__ __forceinline__ void cpasync16(uint32_t dst, const void* src) {
    asm volatile("cp.async.cg.shared.global [%0], [%1], 16;" :: "r"(dst), "l"(src));
}
__device__ __forceinline__ void ldsm4(uint32_t* r, uint32_t addr) {
    asm volatile("ldmatrix.sync.aligned.m8n8.x4.shared.b16 {%0,%1,%2,%3}, [%4];"
                 : "=r"(r[0]), "=r"(r[1]), "=r"(r[2]), "=r"(r[3]) : "r"(addr));
}
__device__ __forceinline__ void mma16816(float* d, const uint32_t* a,
                                         uint32_t b0, uint32_t b1) {
    asm volatile(
        "mma.sync.aligned.m16n8k16.row.col.f32.bf16.bf16.f32 "
        "{%0,%1,%2,%3}, {%4,%5,%6,%7}, {%8,%9}, {%0,%1,%2,%3};"
        : "+f"(d[0]), "+f"(d[1]), "+f"(d[2]), "+f"(d[3])
        : "r"(a[0]), "r"(a[1]), "r"(a[2]), "r"(a[3]), "r"(b0), "r"(b1));
}
__device__ __forceinline__ float ex2f(float x) {
    float r;
    asm("ex2.approx.f32 %0, %1;" : "=f"(r) : "f"(x));
    return r;
}
// bf16 row dot product (16 elems/lane, warp-reduced). Returns scaled dot.
__device__ __forceinline__ float bf16_row_dot(const __nv_bfloat16* a,
                                              const __nv_bfloat16* b, int lane) {
    uint4 xa = reinterpret_cast<const uint4*>(a)[lane];
    uint4 xb = reinterpret_cast<const uint4*>(b)[lane];
    const __nv_bfloat162* pa = reinterpret_cast<const __nv_bfloat162*>(&xa);
    const __nv_bfloat162* pb = reinterpret_cast<const __nv_bfloat162*>(&xb);
    float d = 0.0f;
#pragma unroll
    for (int i = 0; i < 8; i++) {
        float2 fa = __bfloat1622float2(pa[i]);
        float2 fb = __bfloat1622float2(pb[i]);
        d += fa.x * fb.x + fa.y * fb.y;
    }
#pragma unroll
    for (int o = 16; o; o >>= 1) d += __shfl_xor_sync(0xFFFFFFFFu, d, o);
    return d;
}

// ---------------------------------------------------------------------------
// 0) zero rowsums + output scalar
// ---------------------------------------------------------------------------
__global__ void zero_kernel(float* out) {
    int i = blockIdx.x * blockDim.x + threadIdx.x;
    if (i < NLOSS * NN) g_rowsum[i] = 0.0f;
    if (i == 0) out[0] = 0.0f;
}

// ---------------------------------------------------------------------------
// 1) row-normalize all 12 halves; emit scaled bf16 only. One warp per row.
// ---------------------------------------------------------------------------
__global__ void norm_kernel(const float* __restrict__ i0, const float* __restrict__ i1,
                            const float* __restrict__ i2, const float* __restrict__ i3,
                            const float* __restrict__ i4, const float* __restrict__ i5) {
    int gw   = (blockIdx.x * blockDim.x + threadIdx.x) >> 5;
    int lane = threadIdx.x & 31;
    if (gw >= NHALF * BB) return;
    int h = gw / BB;
    int r = gw % BB;
    int m = h >> 1;
    const float* base = (m == 0) ? i0 : (m == 1) ? i1 : (m == 2) ? i2
                       : (m == 3) ? i3 : (m == 4) ? i4 : i5;
    const float* src = base + (size_t)r * 1024 + (size_t)(h & 1) * 512;

    float4 v[4];
    float ss = 0.0f;
#pragma unroll
    for (int w = 0; w < 4; w++) {
        v[w] = reinterpret_cast<const float4*>(src)[lane + w * 32];
        ss += v[w].x * v[w].x + v[w].y * v[w].y + v[w].z * v[w].z + v[w].w * v[w].w;
    }
#pragma unroll
    for (int o = 16; o; o >>= 1) ss += __shfl_xor_sync(0xFFFFFFFFu, ss, o);
    float invk = SCALE_K / fmaxf(sqrtf(ss), 1e-8f);

    __nv_bfloat162* dhi = reinterpret_cast<__nv_bfloat162*>(
        g_zhi + (size_t)h * BB * DD + (size_t)r * DD);
#pragma unroll
    for (int w = 0; w < 4; w++) {
        int pi = (lane + w * 32) * 2;
        dhi[pi]     = __floats2bfloat162_rn(v[w].x * invk, v[w].y * invk);
        dhi[pi + 1] = __floats2bfloat162_rn(v[w].z * invk, v[w].w * invk);
    }
}

// ---------------------------------------------------------------------------
// 2) bf16 HMMA tile kernel: 256x128 sim tile, ex2 epilogue (acc pre-scaled).
//    Grid: x = 272 tiles (I in [0,16) rows-of-256, J>=2I cols-of-128), y = loss.
//    256 threads, 8 warps, warp tile 64x64. Double-buffered cp.async, 96KB smem.
// ---------------------------------------------------------------------------
#define KCHUNK 64
#define ABUF   32768          // 256 rows * 128 bytes
#define BBUF   16384          // 128 rows * 128 bytes
#define STAGE  (ABUF + BBUF)  // 49152
#define SWZOFF(row, seg) ((uint32_t)((row) * 128 + (((seg) ^ ((row) & 7)) << 4)))

__global__ __launch_bounds__(256, 1) void ctile_kernel() {
    extern __shared__ unsigned char smem[];
    const int loss = blockIdx.y;
    int t = blockIdx.x;
    int I = 0;
    while (t >= 32 - 2 * I) { t -= 32 - 2 * I; I++; }
    const int J = 2 * I + t;
    const int r0 = I * 256, c0 = J * 128;
    const int tid = threadIdx.x, wid = tid >> 5, lane = tid & 31;
    const int wm = wid & 3, wn = wid >> 2;

    const __nv_bfloat16* ZA = g_zhi + (size_t)c_cpA[loss] * BB * DD;
    const __nv_bfloat16* ZB = g_zhi + (size_t)c_cpB[loss] * BB * DD;
    const __nv_bfloat16* sA = (r0 < BB) ? ZA + (size_t)r0 * DD : ZB + (size_t)(r0 - BB) * DD;
    const __nv_bfloat16* sB = (c0 < BB) ? ZA + (size_t)c0 * DD : ZB + (size_t)(c0 - BB) * DD;

    const uint32_t sbase = smem_u32(smem);

    float acc[4][8][4];
#pragma unroll
    for (int s = 0; s < 4; s++)
#pragma unroll
        for (int j = 0; j < 8; j++)
#pragma unroll
            for (int g = 0; g < 4; g++) acc[s][j][g] = 0.0f;

    // ---- prologue: prefetch chunk 0 ----
    {
#pragma unroll
        for (int q = tid; q < 2048; q += 256) {
            int row = q >> 3, seg = q & 7;
            cpasync16(sbase + SWZOFF(row, seg), sA + (size_t)row * DD + seg * 8);
        }
#pragma unroll
        for (int q = tid; q < 1024; q += 256) {
            int row = q >> 3, seg = q & 7;
            cpasync16(sbase + ABUF + SWZOFF(row, seg), sB + (size_t)row * DD + seg * 8);
        }
        asm volatile("cp.async.commit_group;" ::: "memory");
    }

    for (int c = 0; c < 8; c++) {
        if (c < 7) {
            const int kc = (c + 1) * KCHUNK;
            const uint32_t dbuf = sbase + ((c + 1) & 1) * STAGE;
#pragma unroll
            for (int q = tid; q < 2048; q += 256) {
                int row = q >> 3, seg = q & 7;
                cpasync16(dbuf + SWZOFF(row, seg), sA + (size_t)row * DD + kc + seg * 8);
            }
#pragma unroll
            for (int q = tid; q < 1024; q += 256) {
                int row = q >> 3, seg = q & 7;
                cpasync16(dbuf + ABUF + SWZOFF(row, seg), sB + (size_t)row * DD + kc + seg * 8);
            }
            asm volatile("cp.async.commit_group;" ::: "memory");
            asm volatile("cp.async.wait_group 1;" ::: "memory");
        } else {
            asm volatile("cp.async.wait_group 0;" ::: "memory");
        }
        __syncthreads();

        const uint32_t ab = sbase + (c & 1) * STAGE;
        const uint32_t bb = ab + ABUF;
#pragma unroll
        for (int kb = 0; kb < 4; kb++) {
            uint32_t af[4][4], bf[4][4];
#pragma unroll
            for (int s = 0; s < 4; s++) {
                int row = wm * 64 + s * 16 + (lane & 15);
                int seg = kb * 2 + (lane >> 4);
                ldsm4(af[s], ab + SWZOFF(row, seg));
            }
#pragma unroll
            for (int p = 0; p < 4; p++) {
                int row = wn * 64 + p * 16 + (lane & 7) + ((lane >> 4) << 3);
                int seg = kb * 2 + ((lane >> 3) & 1);
                ldsm4(bf[p], bb + SWZOFF(row, seg));
            }
#pragma unroll
            for (int s = 0; s < 4; s++)
#pragma unroll
                for (int j = 0; j < 8; j++)
                    mma16816(acc[s][j], af[s], bf[j >> 1][(j & 1) * 2],
                             bf[j >> 1][(j & 1) * 2 + 1]);
        }
        __syncthreads();
    }

    // --------------------------- epilogue ---------------------------
    // acc == sim * TINV * log2(e); exp(sim/T) = ex2(acc)
    const int rl  = lane >> 2;
    const int cl2 = (lane & 3) * 2;
    // sub-block bookkeeping: rb = row 128-block index, J = col 128-block index
    const int rb = 2 * I + (wm >> 1);
    const bool diagW = (rb == J) && ((wm & 1) == wn);   // warp touches diagonal
    const bool colsOK = (rb < J);

    float rp[8], cp[16];

    if (!diagW) {
        __half2 rs01[4], rs23[4], csm[8];
#pragma unroll
        for (int i = 0; i < 4; i++) {
            rs01[i] = __float2half2_rn(0.0f);
            rs23[i] = __float2half2_rn(0.0f);
        }
#pragma unroll
        for (int i = 0; i < 8; i++) csm[i] = __float2half2_rn(0.0f);
#pragma unroll
        for (int s = 0; s < 4; s++)
#pragma unroll
            for (int j = 0; j < 8; j++) {
                __half2 e01 = h2exp2(__floats2half2_rn(acc[s][j][0], acc[s][j][1]));
                __half2 e23 = h2exp2(__floats2half2_rn(acc[s][j][2], acc[s][j][3]));
                rs01[s] = __hadd2(rs01[s], e01);
                rs23[s] = __hadd2(rs23[s], e23);
                csm[j]  = __hadd2(csm[j], __hadd2(e01, e23));
            }
#pragma unroll
        for (int s = 0; s < 4; s++) {
            rp[s * 2]     = __low2float(rs01[s]) + __high2float(rs01[s]);
            rp[s * 2 + 1] = __low2float(rs23[s]) + __high2float(rs23[s]);
        }
#pragma unroll
        for (int j = 0; j < 8; j++) {
            cp[j * 2]     = __low2float(csm[j]);
            cp[j * 2 + 1] = __high2float(csm[j]);
        }
    } else {
        const int rbase = r0 + wm * 64;
        const int cbase = c0 + wn * 64;
#pragma unroll
        for (int i = 0; i < 8; i++) rp[i] = 0.0f;
#pragma unroll
        for (int i = 0; i < 16; i++) cp[i] = 0.0f;
#pragma unroll
        for (int s = 0; s < 4; s++)
#pragma unroll
            for (int j = 0; j < 8; j++)
#pragma unroll
                for (int g = 0; g < 4; g++) {
                    int R = rbase + s * 16 + rl + ((g >> 1) << 3);
                    int C = cbase + j * 8 + cl2 + (g & 1);
                    float e = ex2f(acc[s][j][g]);
                    if (R == C) e = 0.0f;
                    rp[s * 2 + (g >> 1)] += e;
                    cp[j * 2 + (g & 1)]  += e;
                }
    }

#pragma unroll
    for (int i = 0; i < 8; i++) {
        rp[i] += __shfl_xor_sync(0xFFFFFFFFu, rp[i], 1);
        rp[i] += __shfl_xor_sync(0xFFFFFFFFu, rp[i], 2);
    }
#pragma unroll
    for (int i = 0; i < 16; i++) {
        cp[i] += __shfl_xor_sync(0xFFFFFFFFu, cp[i], 4);
        cp[i] += __shfl_xor_sync(0xFFFFFFFFu, cp[i], 8);
        cp[i] += __shfl_xor_sync(0xFFFFFFFFu, cp[i], 16);
    }

    float* rowred = reinterpret_cast<float*>(smem);      // [2][256]
    float* colred = rowred + 512;                        // [4][128]
    if ((lane & 3) == 0) {
#pragma unroll
        for (int s = 0; s < 4; s++)
#pragma unroll
            for (int h = 0; h < 2; h++)
                rowred[wn * 256 + wm * 64 + s * 16 + h * 8 + rl] = rp[s * 2 + h];
    }
    if (lane < 4) {
#pragma unroll
        for (int j = 0; j < 8; j++)
#pragma unroll
            for (int b = 0; b < 2; b++)
                colred[wm * 128 + wn * 64 + j * 8 + cl2 + b] =
                    colsOK ? cp[j * 2 + b] : 0.0f;
    }
    __syncthreads();

    {
        int sub = tid >> 7;                       // 0 or 1 (128-row halves)
        if (2 * I + sub <= J) {
            float rs = rowred[tid] + rowred[256 + tid];
            atomicAdd(&g_rowsum[loss * NN + r0 + tid], rs);
        }
        if (tid < 128 && J > 2 * I) {
            float cs = colred[tid] + colred[128 + tid] + colred[256 + tid] + colred[384 + tid];
            atomicAdd(&g_rowsum[loss * NN + c0 + tid], cs);
        }
    }
}

// ---------------------------------------------------------------------------
// 3) ortho losses: mean(1 - cos) from scaled bf16 rows. One warp per (pair,row).
// ---------------------------------------------------------------------------
__global__ void ortho_kernel(float* out) {
    int gw   = (blockIdx.x * blockDim.x + threadIdx.x) >> 5;
    int lane = threadIdx.x & 31;
    __shared__ float red[8];
    float c = 0.0f;
    if (gw < NORTHO * BB) {
        int p = gw / BB;
        int r = gw % BB;
        const __nv_bfloat16* a = g_zhi + (size_t)c_opA[p] * BB * DD + (size_t)r * DD;
        const __nv_bfloat16* b = g_zhi + (size_t)c_opB[p] * BB * DD + (size_t)r * DD;
        float d = bf16_row_dot(a, b, lane);        // = cos * SCALE_K2
        if (lane == 0) c = (1.0f - d * (1.0f / SCALE_K2)) * (1.0f / (float)BB);
    }
#pragma unroll
    for (int o = 16; o; o >>= 1) c += __shfl_xor_sync(0xFFFFFFFFu, c, o);
    if (lane == 0) red[threadIdx.x >> 5] = c;
    __syncthreads();
    if (threadIdx.x < 8) {
        float v = red[threadIdx.x];
#pragma unroll
        for (int o = 4; o; o >>= 1) v += __shfl_xor_sync(0xFFu, v, o);
        if (threadIdx.x == 0) atomicAdd(out, v);
    }
}

// ---------------------------------------------------------------------------
// 4) finalize contrastive: log(rowsum) minus pos dot (scaled bf16).
// ---------------------------------------------------------------------------
__global__ void finalize_kernel(float* out) {
    int gw   = (blockIdx.x * blockDim.x + threadIdx.x) >> 5;
    int lane = threadIdx.x & 31;
    __shared__ float red[8];
    float c = 0.0f;
    if (gw < NLOSS * NN) {
        int loss = gw / NN;
        int i    = gw % NN;
        float val = logf(g_rowsum[loss * NN + i]);
        if (i < BB) {
            const __nv_bfloat16* a = g_zhi + (size_t)c_cpA[loss] * BB * DD + (size_t)i * DD;
            const __nv_bfloat16* b = g_zhi + (size_t)c_cpB[loss] * BB * DD + (size_t)i * DD;
            float d = bf16_row_dot(a, b, lane);    // = cos * TINV * log2(e)
            val -= 2.0f * d * LN2;                 // = 2 * cos * TINV (both rows)
        }
        if (lane == 0) c = val * (1.0f / (float)NN);
    }
#pragma unroll
    for (int o = 16; o; o >>= 1) c += __shfl_xor_sync(0xFFFFFFFFu, c, o);
    if (lane == 0) red[threadIdx.x >> 5] = c;
    __syncthreads();
    if (threadIdx.x < 8) {
        float v = red[threadIdx.x];
#pragma unroll
        for (int o = 4; o; o >>= 1) v += __shfl_xor_sync(0xFFu, v, o);
        if (threadIdx.x == 0) atomicAdd(out, v);
    }
}

// ---------------------------------------------------------------------------
extern "C" void kernel_launch(void* const* d_in, const int* in_sizes, int n_in,
                              void* d_out, int out_size) {
    (void)in_sizes; (void)n_in; (void)out_size;
    float* out = (float*)d_out;

    cudaFuncSetAttribute(ctile_kernel, cudaFuncAttributeMaxDynamicSharedMemorySize,
                         2 * STAGE);

    zero_kernel<<<(NLOSS * NN + 255) / 256, 256>>>(out);

    norm_kernel<<<(NHALF * BB) / 8, 256>>>(
        (const float*)d_in[0], (const float*)d_in[1], (const float*)d_in[2],
        (const float*)d_in[3], (const float*)d_in[4], (const float*)d_in[5]);

    dim3 grid(272, NLOSS);
    ctile_kernel<<<grid, 256, 2 * STAGE>>>();

    ortho_kernel<<<(NORTHO * BB) / 8, 256>>>(out);
    finalize_kernel<<<(NLOSS * NN) / 8, 256>>>(out);
}

// round 6
// speedup vs baseline: 1.1373x; 1.1373x over previous
#include <cuda_runtime.h>
#include <cuda_bf16.h>
#include <cuda_fp16.h>
#include <math.h>
#include <stdint.h>

// Problem constants
#define BB 2048          // batch
#define NN 4096          // 2*B rows of z
#define DD 512           // half feature dim
#define NHALF 12         // 6 inputs x 2 halves
#define NLOSS 9          // contrastive losses
#define NORTHO 12        // ortho pairs
#define TINV 5.0f        // 1/temperature
// sqrt(TINV * log2(e)) folded into bf16 operands => acc = sim*TINV*log2e
#define SCALE_K  2.6857913787767947f
#define SCALE_K2 7.2134752044448170f   // TINV*log2(e)
#define LN2      0.6931471805599453f

// Scratch (device globals; no allocation allowed)
__device__ __nv_bfloat16 g_zhi[NHALF * BB * DD];   // bf16 normalized * SCALE_K
__device__ float         g_rowsum[NLOSS * NN];     // per-row sum of exp(sim/T)

__constant__ int c_cpA[NLOSS] = {0, 0, 2, 6, 6,  8, 1, 3, 5};
__constant__ int c_cpB[NLOSS] = {2, 4, 4, 8, 10, 10, 7, 9, 11};
__constant__ int c_opA[NORTHO] = {0, 2, 4, 1, 1, 3, 6, 8, 10, 7, 7, 9};
__constant__ int c_opB[NORTHO] = {1, 3, 5, 3, 5, 5, 7, 9, 11, 9, 11, 11};

// ---------------------------------------------------------------------------
__device__ __forceinline__ uint32_t smem_u32(const void* p) {
    uint32_t a;
    asm("{ .reg .u64 t; cvta.to.shared.u64 t, %1; cvt.u32.u64 %0, t; }" : "=r"(a) : "l"(p));
    return a;
}
__device__ __forceinline__ void cpasync16(uint32_t dst, const void* src) {
    asm volatile("cp.async.cg.shared.global [%0], [%1], 16;" :: "r"(dst), "l"(src));
}
__device__ __forceinline__ void ldsm4(uint32_t* r, uint32_t addr) {
    asm volatile("ldmatrix.sync.aligned.m8n8.x4.shared.b16 {%0,%1,%2,%3}, [%4];"
                 : "=r"(r[0]), "=r"(r[1]), "=r"(r[2]), "=r"(r[3]) : "r"(addr));
}
__device__ __forceinline__ void mma16816(float* d, const uint32_t* a,
                                         uint32_t b0, uint32_t b1) {
    asm volatile(
        "mma.sync.aligned.m16n8k16.row.col.f32.bf16.bf16.f32 "
        "{%0,%1,%2,%3}, {%4,%5,%6,%7}, {%8,%9}, {%0,%1,%2,%3};"
        : "+f"(d[0]), "+f"(d[1]), "+f"(d[2]), "+f"(d[3])
        : "r"(a[0]), "r"(a[1]), "r"(a[2]), "r"(a[3]), "r"(b0), "r"(b1));
}
__device__ __forceinline__ float ex2f(float x) {
    float r;
    asm("ex2.approx.f32 %0, %1;" : "=f"(r) : "f"(x));
    return r;
}
// bf16 row dot product (16 elems/lane, warp-reduced). Returns scaled dot.
__device__ __forceinline__ float bf16_row_dot(const __nv_bfloat16* a,
                                              const __nv_bfloat16* b, int lane) {
    uint4 xa = reinterpret_cast<const uint4*>(a)[lane];
    uint4 xb = reinterpret_cast<const uint4*>(b)[lane];
    const __nv_bfloat162* pa = reinterpret_cast<const __nv_bfloat162*>(&xa);
    const __nv_bfloat162* pb = reinterpret_cast<const __nv_bfloat162*>(&xb);
    float d = 0.0f;
#pragma unroll
    for (int i = 0; i < 8; i++) {
        float2 fa = __bfloat1622float2(pa[i]);
        float2 fb = __bfloat1622float2(pb[i]);
        d += fa.x * fb.x + fa.y * fb.y;
    }
#pragma unroll
    for (int o = 16; o; o >>= 1) d += __shfl_xor_sync(0xFFFFFFFFu, d, o);
    return d;
}

// ---------------------------------------------------------------------------
// 0) zero rowsums + output scalar
// ---------------------------------------------------------------------------
__global__ void zero_kernel(float* out) {
    int i = blockIdx.x * blockDim.x + threadIdx.x;
    if (i < NLOSS * NN) g_rowsum[i] = 0.0f;
    if (i == 0) out[0] = 0.0f;
}

// ---------------------------------------------------------------------------
// 1) row-normalize all 12 halves; emit scaled bf16 only. One warp per row.
// ---------------------------------------------------------------------------
__global__ void norm_kernel(const float* __restrict__ i0, const float* __restrict__ i1,
                            const float* __restrict__ i2, const float* __restrict__ i3,
                            const float* __restrict__ i4, const float* __restrict__ i5) {
    int gw   = (blockIdx.x * blockDim.x + threadIdx.x) >> 5;
    int lane = threadIdx.x & 31;
    if (gw >= NHALF * BB) return;
    int h = gw / BB;
    int r = gw % BB;
    int m = h >> 1;
    const float* base = (m == 0) ? i0 : (m == 1) ? i1 : (m == 2) ? i2
                       : (m == 3) ? i3 : (m == 4) ? i4 : i5;
    const float* src = base + (size_t)r * 1024 + (size_t)(h & 1) * 512;

    float4 v[4];
    float ss = 0.0f;
#pragma unroll
    for (int w = 0; w < 4; w++) {
        v[w] = reinterpret_cast<const float4*>(src)[lane + w * 32];
        ss += v[w].x * v[w].x + v[w].y * v[w].y + v[w].z * v[w].z + v[w].w * v[w].w;
    }
#pragma unroll
    for (int o = 16; o; o >>= 1) ss += __shfl_xor_sync(0xFFFFFFFFu, ss, o);
    float invk = SCALE_K / fmaxf(sqrtf(ss), 1e-8f);

    __nv_bfloat162* dhi = reinterpret_cast<__nv_bfloat162*>(
        g_zhi + (size_t)h * BB * DD + (size_t)r * DD);
#pragma unroll
    for (int w = 0; w < 4; w++) {
        int pi = (lane + w * 32) * 2;
        dhi[pi]     = __floats2bfloat162_rn(v[w].x * invk, v[w].y * invk);
        dhi[pi + 1] = __floats2bfloat162_rn(v[w].z * invk, v[w].w * invk);
    }
}

// ---------------------------------------------------------------------------
// 2) bf16 HMMA tile kernel: 128x128 sim tile, ex2 epilogue (acc pre-scaled).
//    Grid: x = 528 upper-triangle tiles, y = loss. 256 threads, 8 warps.
//    Warp tile 64x32. 3-stage cp.async pipeline (96KB smem), occ 2,
//    ONE __syncthreads per K-chunk.
// ---------------------------------------------------------------------------
#define KCHUNK 64
#define BUFSZ  16384          // 128 rows * 128 bytes
#define STAGE  32768          // A + B buffer per stage
#define NSTG   3
#define SWZOFF(row, seg) ((uint32_t)((row) * 128 + (((seg) ^ ((row) & 7)) << 4)))

__global__ __launch_bounds__(256, 2) void ctile_kernel() {
    extern __shared__ unsigned char smem[];
    const int loss = blockIdx.y;
    int t = blockIdx.x;
    int bi = 0;
    while (t >= 32 - bi) { t -= 32 - bi; bi++; }
    const int bj = bi + t;
    const int r0 = bi * 128, c0 = bj * 128;
    const bool diag = (bi == bj);
    const int tid = threadIdx.x, wid = tid >> 5, lane = tid & 31;
    const int wm = wid & 1, wn = wid >> 1;

    const __nv_bfloat16* ZA = g_zhi + (size_t)c_cpA[loss] * BB * DD;
    const __nv_bfloat16* ZB = g_zhi + (size_t)c_cpB[loss] * BB * DD;
    const __nv_bfloat16* sA = (r0 < BB) ? ZA + (size_t)r0 * DD : ZB + (size_t)(r0 - BB) * DD;
    const __nv_bfloat16* sB = (c0 < BB) ? ZA + (size_t)c0 * DD : ZB + (size_t)(c0 - BB) * DD;

    const uint32_t sbase = smem_u32(smem);

    float acc[4][4][4];
#pragma unroll
    for (int s = 0; s < 4; s++)
#pragma unroll
        for (int j = 0; j < 4; j++)
#pragma unroll
            for (int g = 0; g < 4; g++) acc[s][j][g] = 0.0f;

    // per-thread cp.async coords (4 rows x 1 seg each for A and B)
    // q = tid..tid+768 step 256 -> rows, segs
    // ---- prologue: prefetch chunks 0 and 1 into stages 0,1 ----
#pragma unroll
    for (int pc = 0; pc < 2; pc++) {
        const int kc = pc * KCHUNK;
        const uint32_t dbuf = sbase + pc * STAGE;
#pragma unroll
        for (int q = tid; q < 1024; q += 256) {
            int row = q >> 3, seg = q & 7;
            uint32_t off = SWZOFF(row, seg);
            cpasync16(dbuf + off,         sA + (size_t)row * DD + kc + seg * 8);
            cpasync16(dbuf + BUFSZ + off, sB + (size_t)row * DD + kc + seg * 8);
        }
        asm volatile("cp.async.commit_group;" ::: "memory");
    }

    uint32_t stg = 0;   // stage index of chunk c
    for (int c = 0; c < 8; c++) {
        if (c < 7) {
            asm volatile("cp.async.wait_group 1;" ::: "memory");
        } else {
            asm volatile("cp.async.wait_group 0;" ::: "memory");
        }
        __syncthreads();   // stage c visible to all; reads of stage c-1 done

        if (c < 6) {
            const int kc = (c + 2) * KCHUNK;
            uint32_t ds = stg + 2; if (ds >= NSTG) ds -= NSTG;
            const uint32_t dbuf = sbase + ds * STAGE;
#pragma unroll
            for (int q = tid; q < 1024; q += 256) {
                int row = q >> 3, seg = q & 7;
                uint32_t off = SWZOFF(row, seg);
                cpasync16(dbuf + off,         sA + (size_t)row * DD + kc + seg * 8);
                cpasync16(dbuf + BUFSZ + off, sB + (size_t)row * DD + kc + seg * 8);
            }
            asm volatile("cp.async.commit_group;" ::: "memory");
        }

        const uint32_t ab = sbase + stg * STAGE;
        const uint32_t bb = ab + BUFSZ;
#pragma unroll
        for (int kb = 0; kb < 4; kb++) {
            uint32_t af[4][4], bf[2][4];
#pragma unroll
            for (int s = 0; s < 4; s++) {
                int row = wm * 64 + s * 16 + (lane & 15);
                int seg = kb * 2 + (lane >> 4);
                ldsm4(af[s], ab + SWZOFF(row, seg));
            }
#pragma unroll
            for (int p = 0; p < 2; p++) {
                int row = wn * 32 + p * 16 + (lane & 7) + ((lane >> 4) << 3);
                int seg = kb * 2 + ((lane >> 3) & 1);
                ldsm4(bf[p], bb + SWZOFF(row, seg));
            }
#pragma unroll
            for (int s = 0; s < 4; s++)
#pragma unroll
                for (int j = 0; j < 4; j++)
                    mma16816(acc[s][j], af[s], bf[j >> 1][(j & 1) * 2],
                             bf[j >> 1][(j & 1) * 2 + 1]);
        }
        if (++stg >= NSTG) stg = 0;
    }

    // --------------------------- epilogue ---------------------------
    // acc == sim * TINV * log2(e); exp(sim/T) = ex2(acc)
    const int rl  = lane >> 2;          // row within 8-group
    const int cl2 = (lane & 3) * 2;     // col pair base

    float rp[8], cp[8];

    if (!diag) {
        __half2 rs01[4], rs23[4], csm[4];
#pragma unroll
        for (int i = 0; i < 4; i++) {
            rs01[i] = __float2half2_rn(0.0f);
            rs23[i] = __float2half2_rn(0.0f);
            csm[i]  = __float2half2_rn(0.0f);
        }
#pragma unroll
        for (int s = 0; s < 4; s++)
#pragma unroll
            for (int j = 0; j < 4; j++) {
                __half2 e01 = h2exp2(__floats2half2_rn(acc[s][j][0], acc[s][j][1]));
                __half2 e23 = h2exp2(__floats2half2_rn(acc[s][j][2], acc[s][j][3]));
                rs01[s] = __hadd2(rs01[s], e01);
                rs23[s] = __hadd2(rs23[s], e23);
                csm[j]  = __hadd2(csm[j], __hadd2(e01, e23));
            }
#pragma unroll
        for (int s = 0; s < 4; s++) {
            rp[s * 2]     = __low2float(rs01[s]) + __high2float(rs01[s]);
            rp[s * 2 + 1] = __low2float(rs23[s]) + __high2float(rs23[s]);
        }
#pragma unroll
        for (int j = 0; j < 4; j++) {
            cp[j * 2]     = __low2float(csm[j]);
            cp[j * 2 + 1] = __high2float(csm[j]);
        }
    } else {
        const int rbase = r0 + wm * 64;
        const int cbase = c0 + wn * 32;
#pragma unroll
        for (int i = 0; i < 8; i++) { rp[i] = 0.0f; cp[i] = 0.0f; }
#pragma unroll
        for (int s = 0; s < 4; s++)
#pragma unroll
            for (int j = 0; j < 4; j++)
#pragma unroll
                for (int g = 0; g < 4; g++) {
                    int R = rbase + s * 16 + rl + ((g >> 1) << 3);
                    int C = cbase + j * 8 + cl2 + (g & 1);
                    float e = ex2f(acc[s][j][g]);
                    if (R == C) e = 0.0f;
                    rp[s * 2 + (g >> 1)] += e;
                    cp[j * 2 + (g & 1)]  += e;
                }
    }

#pragma unroll
    for (int i = 0; i < 8; i++) {
        rp[i] += __shfl_xor_sync(0xFFFFFFFFu, rp[i], 1);
        rp[i] += __shfl_xor_sync(0xFFFFFFFFu, rp[i], 2);
    }
#pragma unroll
    for (int i = 0; i < 8; i++) {
        cp[i] += __shfl_xor_sync(0xFFFFFFFFu, cp[i], 4);
        cp[i] += __shfl_xor_sync(0xFFFFFFFFu, cp[i], 8);
        cp[i] += __shfl_xor_sync(0xFFFFFFFFu, cp[i], 16);
    }

    // reduction buffers reuse stage-0 smem (no longer read: holds chunk 6)
    float* rowred = reinterpret_cast<float*>(smem);      // [4][128]
    float* colred = rowred + 512;                        // [2][128]
    __syncthreads();   // all warps out of mainloop before reuse
    if ((lane & 3) == 0) {
#pragma unroll
        for (int s = 0; s < 4; s++)
#pragma unroll
            for (int h = 0; h < 2; h++)
                rowred[wn * 128 + wm * 64 + s * 16 + h * 8 + rl] = rp[s * 2 + h];
    }
    if (lane < 4) {
#pragma unroll
        for (int j = 0; j < 4; j++)
#pragma unroll
            for (int b = 0; b < 2; b++)
                colred[wm * 128 + wn * 32 + j * 8 + cl2 + b] = cp[j * 2 + b];
    }
    __syncthreads();

    if (tid < 128) {
        float rs = rowred[tid] + rowred[128 + tid] + rowred[256 + tid] + rowred[384 + tid];
        atomicAdd(&g_rowsum[loss * NN + r0 + tid], rs);
        if (!diag) {
            float cs = colred[tid] + colred[128 + tid];
            atomicAdd(&g_rowsum[loss * NN + c0 + tid], cs);
        }
    }
}

// ---------------------------------------------------------------------------
// 3) ortho losses: mean(1 - cos) from scaled bf16 rows. One warp per (pair,row).
// ---------------------------------------------------------------------------
__global__ void ortho_kernel(float* out) {
    int gw   = (blockIdx.x * blockDim.x + threadIdx.x) >> 5;
    int lane = threadIdx.x & 31;
    __shared__ float red[8];
    float c = 0.0f;
    if (gw < NORTHO * BB) {
        int p = gw / BB;
        int r = gw % BB;
        const __nv_bfloat16* a = g_zhi + (size_t)c_opA[p] * BB * DD + (size_t)r * DD;
        const __nv_bfloat16* b = g_zhi + (size_t)c_opB[p] * BB * DD + (size_t)r * DD;
        float d = bf16_row_dot(a, b, lane);        // = cos * SCALE_K2
        if (lane == 0) c = (1.0f - d * (1.0f / SCALE_K2)) * (1.0f / (float)BB);
    }
#pragma unroll
    for (int o = 16; o; o >>= 1) c += __shfl_xor_sync(0xFFFFFFFFu, c, o);
    if (lane == 0) red[threadIdx.x >> 5] = c;
    __syncthreads();
    if (threadIdx.x < 8) {
        float v = red[threadIdx.x];
#pragma unroll
        for (int o = 4; o; o >>= 1) v += __shfl_xor_sync(0xFFu, v, o);
        if (threadIdx.x == 0) atomicAdd(out, v);
    }
}

// ---------------------------------------------------------------------------
// 4) finalize contrastive: log(rowsum) minus pos dot (scaled bf16).
// ---------------------------------------------------------------------------
__global__ void finalize_kernel(float* out) {
    int gw   = (blockIdx.x * blockDim.x + threadIdx.x) >> 5;
    int lane = threadIdx.x & 31;
    __shared__ float red[8];
    float c = 0.0f;
    if (gw < NLOSS * NN) {
        int loss = gw / NN;
        int i    = gw % NN;
        float val = logf(g_rowsum[loss * NN + i]);
        if (i < BB) {
            const __nv_bfloat16* a = g_zhi + (size_t)c_cpA[loss] * BB * DD + (size_t)i * DD;
            const __nv_bfloat16* b = g_zhi + (size_t)c_cpB[loss] * BB * DD + (size_t)i * DD;
            float d = bf16_row_dot(a, b, lane);    // = cos * TINV * log2(e)
            val -= 2.0f * d * LN2;                 // = 2 * cos * TINV (both rows)
        }
        if (lane == 0) c = val * (1.0f / (float)NN);
    }
#pragma unroll
    for (int o = 16; o; o >>= 1) c += __shfl_xor_sync(0xFFFFFFFFu, c, o);
    if (lane == 0) red[threadIdx.x >> 5] = c;
    __syncthreads();
    if (threadIdx.x < 8) {
        float v = red[threadIdx.x];
#pragma unroll
        for (int o = 4; o; o >>= 1) v += __shfl_xor_sync(0xFFu, v, o);
        if (threadIdx.x == 0) atomicAdd(out, v);
    }
}

// ---------------------------------------------------------------------------
extern "C" void kernel_launch(void* const* d_in, const int* in_sizes, int n_in,
                              void* d_out, int out_size) {
    (void)in_sizes; (void)n_in; (void)out_size;
    float* out = (float*)d_out;

    cudaFuncSetAttribute(ctile_kernel, cudaFuncAttributeMaxDynamicSharedMemorySize,
                         NSTG * STAGE);

    zero_kernel<<<(NLOSS * NN + 255) / 256, 256>>>(out);

    norm_kernel<<<(NHALF * BB) / 8, 256>>>(
        (const float*)d_in[0], (const float*)d_in[1], (const float*)d_in[2],
        (const float*)d_in[3], (const float*)d_in[4], (const float*)d_in[5]);

    dim3 grid(528, NLOSS);
    ctile_kernel<<<grid, 256, NSTG * STAGE>>>();

    ortho_kernel<<<(NORTHO * BB) / 8, 256>>>(out);
    finalize_kernel<<<(NLOSS * NN) / 8, 256>>>(out);
}